// round 10
// baseline (speedup 1.0000x reference)
#include <cuda_runtime.h>
#include <cuda_bf16.h>

// MultiHeadAttentionRelative: B=8192, J=81, DIM=128, HEADS=4, head_dim=32
// out[b,0,:] = concat_h( softmax_j( (Q.K + Q.Kr + Qr.K) * SCALE )_h @ V_h )
//
// HBM-bound (~1.37 GB mandatory stream). R9: persistent grid-stride launch —
// grid = 148 SMs * 9 CTAs/SM = 1332 (exactly one wave at 56-reg occupancy);
// each CTA loops over ~6.15 batches. Removes 6.15 waves of CTA launch/
// teardown + the 200-CTA tail wave + wave transitions, keeping DRAM
// uniformly loaded start-to-finish. Inner loop is byte-identical to the
// measured-best R4 body (single pass, max-free softmax, warp-strided j,
// natural register schedule).

#define B_TOTAL 8192
#define J_LEN   81
#define DIM_    128
#define HEADS_  4
#define GRID_PERSIST (148 * 9)
// SCALE = (DIM/HEADS)^-0.5 = 1/sqrt(32)
#define SCALE_F 0.17677669529663687f

__global__ void __launch_bounds__(128)
mhar_kernel(const float* __restrict__ Q,
            const float* __restrict__ K,
            const float* __restrict__ V,
            const float* __restrict__ Qr,
            const float* __restrict__ Kr,
            float* __restrict__ out)
{
    const int t    = threadIdx.x;
    const int lane = t & 31;
    const int warp = t >> 5;
    const int h    = lane >> 3;   // head owning dims [4*lane, 4*lane+4)

    __shared__ float s_sum[4][HEADS_];
    __shared__ float s_acc[4][DIM_];

    for (int b = blockIdx.x; b < B_TOTAL; b += GRID_PERSIST) {

        // Q row: lane holds dims [4*lane, 4*lane+4)
        const float4 q4 = reinterpret_cast<const float4*>(Q + (size_t)b * DIM_)[lane];

        const size_t base = (size_t)b * J_LEN * DIM_;
        const float4* Kb  = reinterpret_cast<const float4*>(K  + base);
        const float4* Vb  = reinterpret_cast<const float4*>(V  + base);
        const float4* Qrb = reinterpret_cast<const float4*>(Qr + base);
        const float4* Krb = reinterpret_cast<const float4*>(Kr + base);

        // ---- single streaming pass: score + exp + weighted-V accumulate ----
        float  s_run = 0.f;
        float4 acc   = make_float4(0.f, 0.f, 0.f, 0.f);

        // warp w handles rows j = w, w+4, w+8, ...
        #pragma unroll 3
        for (int j = warp; j < J_LEN; j += 4) {
            const int idx = j * 32 + lane;
            const float4 k4  = Kb[idx];
            const float4 kr4 = Krb[idx];
            const float4 qr4 = Qrb[idx];
            const float4 v4  = Vb[idx];

            // fused c_c + c_p + p_c partial dot (this lane's 4 dims)
            float s;
            s  = q4.x * k4.x;           s = fmaf(q4.y,  k4.y,  s);
            s  = fmaf(q4.z,  k4.z,  s); s = fmaf(q4.w,  k4.w,  s);
            s  = fmaf(q4.x,  kr4.x, s); s = fmaf(q4.y,  kr4.y, s);
            s  = fmaf(q4.z,  kr4.z, s); s = fmaf(q4.w,  kr4.w, s);
            s  = fmaf(qr4.x, k4.x,  s); s = fmaf(qr4.y, k4.y,  s);
            s  = fmaf(qr4.z, k4.z,  s); s = fmaf(qr4.w, k4.w,  s);

            // butterfly-reduce within the 8-lane head group
            s += __shfl_xor_sync(0xffffffffu, s, 1);
            s += __shfl_xor_sync(0xffffffffu, s, 2);
            s += __shfl_xor_sync(0xffffffffu, s, 4);

            // max-free softmax term: exp(s*SCALE) directly
            const float p = __expf(s * SCALE_F);
            s_run += p;
            acc.x = fmaf(p, v4.x, acc.x);
            acc.y = fmaf(p, v4.y, acc.y);
            acc.z = fmaf(p, v4.z, acc.z);
            acc.w = fmaf(p, v4.w, acc.w);
        }

        // ---- publish per-warp partials ----
        if ((lane & 7) == 0)
            s_sum[warp][h] = s_run;
        reinterpret_cast<float4*>(s_acc[warp])[lane] = acc;
        __syncthreads();

        // ---- warp 0 combines the 4 warps' (sum, acc) per head ----
        if (warp == 0) {
            const float T = (s_sum[0][h] + s_sum[1][h]) + (s_sum[2][h] + s_sum[3][h]);
            const float inv = __frcp_rn(T);

            const float4 a0 = reinterpret_cast<const float4*>(s_acc[0])[lane];
            const float4 a1 = reinterpret_cast<const float4*>(s_acc[1])[lane];
            const float4 a2 = reinterpret_cast<const float4*>(s_acc[2])[lane];
            const float4 a3 = reinterpret_cast<const float4*>(s_acc[3])[lane];

            float4 r;
            r.x = ((a0.x + a1.x) + (a2.x + a3.x)) * inv;
            r.y = ((a0.y + a1.y) + (a2.y + a3.y)) * inv;
            r.z = ((a0.z + a1.z) + (a2.z + a3.z)) * inv;
            r.w = ((a0.w + a1.w) + (a2.w + a3.w)) * inv;
            reinterpret_cast<float4*>(out + (size_t)b * DIM_)[lane] = r;
        }
        __syncthreads();   // WAR: next batch rewrites s_acc/s_sum
    }
}

extern "C" void kernel_launch(void* const* d_in, const int* in_sizes, int n_in,
                              void* d_out, int out_size)
{
    const float* Q  = (const float*)d_in[0];
    const float* K  = (const float*)d_in[1];
    const float* V  = (const float*)d_in[2];
    const float* Qr = (const float*)d_in[3];
    const float* Kr = (const float*)d_in[4];
    float* out = (float*)d_out;

    mhar_kernel<<<GRID_PERSIST, 128>>>(Q, K, V, Qr, Kr, out);
}

// round 12
// speedup vs baseline: 1.1478x; 1.1478x over previous
#include <cuda_runtime.h>
#include <cuda_bf16.h>

// MultiHeadAttentionRelative: B=8192, J=81, DIM=128, HEADS=4, head_dim=32
// out[b,0,:] = concat_h( softmax_j( (Q.K + Q.Kr + Qr.K) * SCALE )_h @ V_h )
//
// HBM-bound (~1.37 GB mandatory stream). FINAL (= R4, measured best:
// 195.1us / 89.0% DRAM / 7052 GB/s; rerun 198.2us — ±1.5% run noise).
// Single streaming pass fusing all three score dots + V accumulate,
// max-free softmax (scores bounded ~15 << 88 so exp(s) direct — no serial
// online-max recurrence), warp-strided j, one CTA per batch row, natural
// 56-reg compiler schedule.
//
// Measured-and-rejected alternatives: 2-batch ILP (R3 215us: reg pressure +
// L1tex-queue spread), reg caps 40/48 (R5 200us / R7 201us: load-batching
// collapse / spills), contiguous chunks + __ldcs (R6 197us), persistent
// grid-stride (R9 226us: regs->40 + per-batch barrier drain). This
// configuration is the hill-top; all compute pipes <15%, duration ==
// bytes / achieved-BW at the chip's streaming ceiling.

#define B_TOTAL 8192
#define J_LEN   81
#define DIM_    128
#define HEADS_  4
// SCALE = (DIM/HEADS)^-0.5 = 1/sqrt(32)
#define SCALE_F 0.17677669529663687f

__global__ void __launch_bounds__(128)
mhar_kernel(const float* __restrict__ Q,
            const float* __restrict__ K,
            const float* __restrict__ V,
            const float* __restrict__ Qr,
            const float* __restrict__ Kr,
            float* __restrict__ out)
{
    const int b    = blockIdx.x;
    const int t    = threadIdx.x;
    const int lane = t & 31;
    const int warp = t >> 5;
    const int h    = lane >> 3;   // head owning dims [4*lane, 4*lane+4)

    __shared__ float s_sum[4][HEADS_];
    __shared__ float s_acc[4][DIM_];

    // Q row: lane holds dims [4*lane, 4*lane+4)
    const float4 q4 = reinterpret_cast<const float4*>(Q + (size_t)b * DIM_)[lane];

    const size_t base = (size_t)b * J_LEN * DIM_;
    const float4* Kb  = reinterpret_cast<const float4*>(K  + base);
    const float4* Vb  = reinterpret_cast<const float4*>(V  + base);
    const float4* Qrb = reinterpret_cast<const float4*>(Qr + base);
    const float4* Krb = reinterpret_cast<const float4*>(Kr + base);

    // ---- single streaming pass: score + exp + weighted-V accumulate ----
    float  s_run = 0.f;
    float4 acc   = make_float4(0.f, 0.f, 0.f, 0.f);

    // warp w handles rows j = w, w+4, w+8, ...
    #pragma unroll 3
    for (int j = warp; j < J_LEN; j += 4) {
        const int idx = j * 32 + lane;
        const float4 k4  = Kb[idx];
        const float4 kr4 = Krb[idx];
        const float4 qr4 = Qrb[idx];
        const float4 v4  = Vb[idx];

        // fused c_c + c_p + p_c partial dot (this lane's 4 dims)
        float s;
        s  = q4.x * k4.x;           s = fmaf(q4.y,  k4.y,  s);
        s  = fmaf(q4.z,  k4.z,  s); s = fmaf(q4.w,  k4.w,  s);
        s  = fmaf(q4.x,  kr4.x, s); s = fmaf(q4.y,  kr4.y, s);
        s  = fmaf(q4.z,  kr4.z, s); s = fmaf(q4.w,  kr4.w, s);
        s  = fmaf(qr4.x, k4.x,  s); s = fmaf(qr4.y, k4.y,  s);
        s  = fmaf(qr4.z, k4.z,  s); s = fmaf(qr4.w, k4.w,  s);

        // butterfly-reduce within the 8-lane head group (all lanes get sum)
        s += __shfl_xor_sync(0xffffffffu, s, 1);
        s += __shfl_xor_sync(0xffffffffu, s, 2);
        s += __shfl_xor_sync(0xffffffffu, s, 4);

        // max-free softmax term: exp(s*SCALE) directly; no loop-carried
        // recurrence except the plain accumulation adds
        const float p = __expf(s * SCALE_F);
        s_run += p;
        acc.x = fmaf(p, v4.x, acc.x);
        acc.y = fmaf(p, v4.y, acc.y);
        acc.z = fmaf(p, v4.z, acc.z);
        acc.w = fmaf(p, v4.w, acc.w);
    }

    // ---- publish per-warp partials ----
    if ((lane & 7) == 0)
        s_sum[warp][h] = s_run;
    reinterpret_cast<float4*>(s_acc[warp])[lane] = acc;
    __syncthreads();

    // ---- warp 0 combines the 4 warps' (sum, acc) per head ----
    if (warp == 0) {
        const float T = (s_sum[0][h] + s_sum[1][h]) + (s_sum[2][h] + s_sum[3][h]);
        const float inv = __frcp_rn(T);

        const float4 a0 = reinterpret_cast<const float4*>(s_acc[0])[lane];
        const float4 a1 = reinterpret_cast<const float4*>(s_acc[1])[lane];
        const float4 a2 = reinterpret_cast<const float4*>(s_acc[2])[lane];
        const float4 a3 = reinterpret_cast<const float4*>(s_acc[3])[lane];

        float4 r;
        r.x = ((a0.x + a1.x) + (a2.x + a3.x)) * inv;
        r.y = ((a0.y + a1.y) + (a2.y + a3.y)) * inv;
        r.z = ((a0.z + a1.z) + (a2.z + a3.z)) * inv;
        r.w = ((a0.w + a1.w) + (a2.w + a3.w)) * inv;
        reinterpret_cast<float4*>(out + (size_t)b * DIM_)[lane] = r;
    }
}

extern "C" void kernel_launch(void* const* d_in, const int* in_sizes, int n_in,
                              void* d_out, int out_size)
{
    const float* Q  = (const float*)d_in[0];
    const float* K  = (const float*)d_in[1];
    const float* V  = (const float*)d_in[2];
    const float* Qr = (const float*)d_in[3];
    const float* Kr = (const float*)d_in[4];
    float* out = (float*)d_out;

    mhar_kernel<<<B_TOTAL, 128>>>(Q, K, V, Qr, Kr, out);
}